// round 8
// baseline (speedup 1.0000x reference)
#include <cuda_runtime.h>
#include <math.h>

#define VOL    110592   // 48*48*48
#define HV     55296    // VOL/2
#define PLANE  2304     // 48*48
#define NVOX   221184   // B * VOL
#define TOTALE 884736   // B*C*VOL
#define INF9   1.0e9f
#define LUTN   6640
#define LOSSBLKS 432    // NVOX / 2 / 256

// Static scratch (no allocations allowed)
__device__ unsigned short g_bufS1[8 * VOL];  // pos^2 after W+H (ushort, clamped)
__device__ unsigned short g_bufS2[8 * VOL];  // pos^2 after W+H+D (ushort, clamped)
__device__ float  g_lut[LUTN];
__device__ int    g_flags[8];   // zero-init; reset by loss epilogue each replay
__device__ int    g_count;      // zero-init; reset by loss epilogue each replay
__device__ double g_partials[LOSSBLKS];

// ---------------------------------------------------------------------------
// Kernel A: one block per (b,d) plane, 768 threads = 4 class-groups of 192.
// Self-detects dtype, loads labels ONCE, per-class line masks, exact W-EDT
// via clz/ffs, exact H min-plus. Stores W+H squared dists as ushort.
// Block 0 also builds the sqrt LUT (consumed two kernels later).
// ---------------------------------------------------------------------------
__global__ void __launch_bounds__(768) kA(const void* __restrict__ target) {
    __shared__ unsigned char lab[PLANE];
    __shared__ unsigned long long lmask[4][48];
    __shared__ float s[4][48][49];
    __shared__ int sbad;
    __shared__ int anyf[4];

    const int tid = threadIdx.x;
    const int bd = blockIdx.x;
    const int b = bd / 48;
    const int d = bd - b * 48;
    const int cgrp = tid / 192;       // class
    const int t = tid - cgrp * 192;

    if (tid == 0) sbad = 0;
    if (tid < 4) anyf[tid] = 0;
    if (tid < 192) ((unsigned long long*)lmask)[tid] = 0ULL;
    __syncthreads();

    // dtype detection from the first 512 bytes (in-bounds for both dtypes).
    if (tid < 64) {
        long long v = ((const long long*)target)[tid];
        if (v < 0 || v > 3) atomicOr(&sbad, 1);
    }
    __syncthreads();
    const bool is64 = (sbad == 0);

    // Load this (b,d) plane's labels once.
    const int vbase = b * VOL + d * PLANE;
    if (is64) {
        const long long* tp = (const long long*)target;
        for (int i = tid; i < PLANE; i += 768) lab[i] = (unsigned char)tp[vbase + i];
    } else {
        const int* tp = (const int*)target;
        for (int i = tid; i < PLANE; i += 768) lab[i] = (unsigned char)tp[vbase + i];
    }
    __syncthreads();

    // Per-class line masks.
    {
        int h = t >> 2;
        int w0 = (t & 3) * 12;
        unsigned long long bits = 0ULL;
        #pragma unroll
        for (int k = 0; k < 12; k++) {
            int w = w0 + k;
            unsigned long long isc =
                (unsigned long long)(lab[h * 48 + w] == (unsigned char)cgrp);
            bits |= isc << w;
        }
        if (bits) { atomicOr(&lmask[cgrp][h], bits); anyf[cgrp] = 1; }
    }
    __syncthreads();
    if (t == 0 && anyf[cgrp]) atomicOr(&g_flags[b * 4 + cgrp], 1);

    // Block 0 builds the sqrt LUT.
    if (bd == 0) {
        for (int i = tid; i < LUTN; i += 768) g_lut[i] = sqrtf((float)i);
    }

    // Exact W distances via clz/ffs; fold +h^2 for the H pass.
    #pragma unroll
    for (int k = 0; k < 12; k++) {
        int i = t + k * 192;
        int hh = i / 48;
        int ww = i - hh * 48;
        unsigned long long mm = lmask[cgrp][hh];
        unsigned long long lowm = mm << (63 - ww);
        unsigned long long him  = mm >> ww;
        int dl = lowm ? __clzll(lowm) : 99;
        int dr = him ? (__ffsll(him) - 1) : 99;
        int dd = min(dl, dr);
        float v = (dd <= 47) ? (float)(dd * dd) : INF9;
        s[cgrp][hh][ww] = v + (float)(hh * hh);
    }
    __syncthreads();

    // H min-plus: within group, grp owns 12 outputs x; lane = w.
    const int grp = t & 3;
    const int lane = t >> 2;
    float acc[12], xv[12];
    #pragma unroll
    for (int k = 0; k < 12; k++) { acc[k] = 1.0e30f; xv[k] = (float)(grp * 12 + k); }

    #pragma unroll
    for (int jc = 0; jc < 4; jc++) {
        float sv[12];
        #pragma unroll
        for (int tt = 0; tt < 12; tt++) sv[tt] = s[cgrp][jc * 12 + tt][lane];
        #pragma unroll
        for (int tt = 0; tt < 12; tt++) {
            const float cj = -2.0f * (float)(jc * 12 + tt);
            #pragma unroll
            for (int k = 0; k < 12; k++)
                acc[k] = fminf(acc[k], fmaf(cj, xv[k], sv[tt]));
        }
    }

    const int base = (b * 4 + cgrp) * VOL + d * PLANE;
    #pragma unroll
    for (int k = 0; k < 12; k++) {
        int x = grp * 12 + k;
        float val = acc[k] + (float)(x * x);
        g_bufS1[base + x * 48 + lane] = (unsigned short)fminf(val, 65535.0f);
    }
}

// ---------------------------------------------------------------------------
// Kernel B: exact D min-plus. One block per (m, h) plane (d, w), 192 threads.
// ushort in -> ushort out (present-class values exact, <= 6627).
// ---------------------------------------------------------------------------
__global__ void __launch_bounds__(192) kB() {
    __shared__ float s[48][49];
    const int tid = threadIdx.x;
    const int m = blockIdx.x / 48;
    const int h = blockIdx.x - m * 48;
    const int base = m * VOL + h * 48;

    for (int i = tid; i < PLANE; i += 192) {
        int dd = i / 48;
        int w = i - dd * 48;
        s[dd][w] = (float)g_bufS1[base + dd * PLANE + w] + (float)(dd * dd);
    }
    __syncthreads();

    const int grp = tid & 3;
    const int lane = tid >> 2;
    float acc[12], xv[12];
    #pragma unroll
    for (int k = 0; k < 12; k++) { acc[k] = 1.0e30f; xv[k] = (float)(grp * 12 + k); }

    #pragma unroll
    for (int jc = 0; jc < 4; jc++) {
        float sv[12];
        #pragma unroll
        for (int t = 0; t < 12; t++) sv[t] = s[jc * 12 + t][lane];
        #pragma unroll
        for (int t = 0; t < 12; t++) {
            const float cj = -2.0f * (float)(jc * 12 + t);
            #pragma unroll
            for (int k = 0; k < 12; k++)
                acc[k] = fminf(acc[k], fmaf(cj, xv[k], sv[t]));
        }
    }

    #pragma unroll
    for (int k = 0; k < 12; k++) {
        int x = grp * 12 + k;
        float val = acc[k] + (float)(x * x);
        g_bufS2[base + x * PLANE + lane] = (unsigned short)fminf(val, 65535.0f);
    }
}

// ---------------------------------------------------------------------------
// Loss: 2 voxels/thread (float2 pred, ushort2 dist, front-batched MLP=8).
// q_c = LUT[pos2_c]; |sdf_c| = q_c + min_{c'!=c} q_{c'} (exact: one term 0,
// min commutes with sqrt). Branch-free flag multipliers. Deterministic
// double reduction; last block finishes + resets globals for next replay.
// ---------------------------------------------------------------------------
__global__ void __launch_bounds__(256) k_loss(const float* __restrict__ pred,
                                              float* __restrict__ out) {
    const int t = blockIdx.x * 256 + threadIdx.x;   // 0..110591
    const int b = t / HV;
    const int r = t - b * HV;
    const int base2 = b * 4 * HV + r;

    const float2*  p2 = (const float2*)pred;
    const ushort2* q2 = (const ushort2*)g_bufS2;

    float2  P[4];
    ushort2 Dv[4];
    #pragma unroll
    for (int c = 0; c < 4; c++) P[c] = __ldg(&p2[base2 + c * HV]);
    #pragma unroll
    for (int c = 0; c < 4; c++) Dv[c] = __ldg(&q2[base2 + c * HV]);

    float fl[4];
    #pragma unroll
    for (int c = 0; c < 4; c++) fl[c] = g_flags[b * 4 + c] ? 1.0f : 0.0f;

    double sum = 0.0;
    #pragma unroll
    for (int v = 0; v < 2; v++) {
        float p0 = v ? P[0].y : P[0].x;
        float p1 = v ? P[1].y : P[1].x;
        float p2v = v ? P[2].y : P[2].x;
        float p3 = v ? P[3].y : P[3].x;
        int i0 = v ? Dv[0].y : Dv[0].x;
        int i1 = v ? Dv[1].y : Dv[1].x;
        int i2 = v ? Dv[2].y : Dv[2].x;
        int i3 = v ? Dv[3].y : Dv[3].x;

        float q0 = (i0 < LUTN) ? __ldg(&g_lut[i0]) : sqrtf((float)i0);
        float q1 = (i1 < LUTN) ? __ldg(&g_lut[i1]) : sqrtf((float)i1);
        float q2c = (i2 < LUTN) ? __ldg(&g_lut[i2]) : sqrtf((float)i2);
        float q3 = (i3 < LUTN) ? __ldg(&g_lut[i3]) : sqrtf((float)i3);

        float mx = fmaxf(fmaxf(p0, p1), fmaxf(p2v, p3));
        float e0 = __expf(p0 - mx);
        float e1 = __expf(p1 - mx);
        float e2 = __expf(p2v - mx);
        float e3 = __expf(p3 - mx);
        float inv = __fdividef(1.0f, e0 + e1 + e2 + e3);

        float m01 = fminf(q0, q1), m23 = fminf(q2c, q3);
        float s0 = q0 + fminf(q1, m23);
        float s1 = q1 + fminf(q0, m23);
        float s2 = q2c + fminf(m01, q3);
        float s3 = q3 + fminf(m01, q2c);

        float local = fl[0] * e0 * s0 + fl[1] * e1 * s1
                    + fl[2] * e2 * s2 + fl[3] * e3 * s3;
        sum += (double)(local * inv);
    }

    __shared__ double sh[256];
    __shared__ int islast;
    sh[threadIdx.x] = sum;
    __syncthreads();
    #pragma unroll
    for (int st = 128; st > 0; st >>= 1) {
        if (threadIdx.x < st) sh[threadIdx.x] += sh[threadIdx.x + st];
        __syncthreads();
    }
    if (threadIdx.x == 0) {
        g_partials[blockIdx.x] = sh[0];
        __threadfence();
        int done = atomicAdd(&g_count, 1);
        islast = (done == gridDim.x - 1);
    }
    __syncthreads();

    if (islast) {
        int i2n = threadIdx.x + 256;
        double v = g_partials[threadIdx.x]
                 + ((i2n < LOSSBLKS) ? g_partials[i2n] : 0.0);
        sh[threadIdx.x] = v;
        __syncthreads();
        #pragma unroll
        for (int st = 128; st > 0; st >>= 1) {
            if (threadIdx.x < st) sh[threadIdx.x] += sh[threadIdx.x + st];
            __syncthreads();
        }
        if (threadIdx.x == 0) {
            out[0] = (float)(sh[0] / (double)TOTALE);
            g_count = 0;                    // reset for next graph replay
        }
        if (threadIdx.x < 8) g_flags[threadIdx.x] = 0;
    }
}

// ---------------------------------------------------------------------------
extern "C" void kernel_launch(void* const* d_in, const int* in_sizes, int n_in,
                              void* d_out, int out_size) {
    const float* pred   = (const float*)d_in[0];
    const void*  target = d_in[1];
    float* out = (float*)d_out;

    kA<<<96, 768>>>(target);            // labels once -> W bit-scan + H min-plus
    kB<<<8 * 48, 192>>>();              // D min-plus (ushort)
    k_loss<<<LOSSBLKS, 256>>>(pred, out);
}

// round 9
// speedup vs baseline: 1.1604x; 1.1604x over previous
#include <cuda_runtime.h>
#include <math.h>

#define VOL    110592   // 48*48*48
#define HV     55296    // VOL/2
#define PLANE  2304     // 48*48
#define NVOX   221184   // B * VOL
#define TOTALE 884736   // B*C*VOL
#define LUTN   6640
#define U16INF 50000    // 'infinity' in u16 domain; max transient 54418 < 65535
#define LOSSBLKS 432    // NVOX / 2 / 256

// Static scratch (no allocations allowed)
__device__ unsigned short g_bufS1[8 * VOL];  // pos^2 after W+H (u16)
__device__ unsigned short g_bufS2[8 * VOL];  // pos^2 after W+H+D (u16)
__device__ float  g_lut[LUTN];
__device__ int    g_flags[8];   // zero-init; reset by loss epilogue each replay
__device__ int    g_count;      // zero-init; reset by loss epilogue each replay
__device__ double g_partials[LOSSBLKS];

// psq table layout: entry ((j*4 + grp)*8 + kk), kk in [0,6):
//   x0 = grp*12 + 2*kk;  packed ( (x0-j)^2 , (x0+1-j)^2 )
__device__ __forceinline__ void fill_psq(unsigned int* psq, int tid, int nthr) {
    for (int i = tid; i < 48 * 4 * 8; i += nthr) {
        int j  = i >> 5;
        int g  = (i >> 3) & 3;
        int kk = i & 7;
        unsigned int val = 0;
        if (kk < 6) {
            int x0 = g * 12 + 2 * kk;
            int d0 = x0 - j;
            int d1 = d0 + 1;
            val = (unsigned int)(d0 * d0) | ((unsigned int)(d1 * d1) << 16);
        }
        psq[i] = val;
    }
}

// ---------------------------------------------------------------------------
// Kernel A: one block per (b,d) plane, 768 threads = 4 class-groups of 192.
// dtype detect, labels once, per-class line masks, exact W-EDT via clz/ffs
// (u16 results), exact H min-plus via DPX viaddmin on packed u16x2.
// Block 0 also builds the sqrt LUT.
// ---------------------------------------------------------------------------
__global__ void __launch_bounds__(768) kA(const void* __restrict__ target) {
    __shared__ unsigned char lab[PLANE];
    __shared__ unsigned long long lmask[4][48];
    __shared__ unsigned short us[4][48][50];
    __shared__ unsigned int psq[48 * 4 * 8];
    __shared__ int sbad;
    __shared__ int anyf[4];

    const int tid = threadIdx.x;
    const int bd = blockIdx.x;
    const int b = bd / 48;
    const int d = bd - b * 48;
    const int cgrp = tid / 192;       // class
    const int t = tid - cgrp * 192;

    if (tid == 0) sbad = 0;
    if (tid < 4) anyf[tid] = 0;
    if (tid < 192) ((unsigned long long*)lmask)[tid] = 0ULL;
    __syncthreads();

    // dtype detection from the first 512 bytes (in-bounds for both dtypes).
    if (tid < 64) {
        long long v = ((const long long*)target)[tid];
        if (v < 0 || v > 3) atomicOr(&sbad, 1);
    }
    __syncthreads();
    const bool is64 = (sbad == 0);

    // Load this (b,d) plane's labels once.
    const int vbase = b * VOL + d * PLANE;
    if (is64) {
        const long long* tp = (const long long*)target;
        for (int i = tid; i < PLANE; i += 768) lab[i] = (unsigned char)tp[vbase + i];
    } else {
        const int* tp = (const int*)target;
        for (int i = tid; i < PLANE; i += 768) lab[i] = (unsigned char)tp[vbase + i];
    }
    // Fill packed squares table while labels land.
    fill_psq(psq, tid, 768);
    __syncthreads();

    // Per-class line masks.
    {
        int h = t >> 2;
        int w0 = (t & 3) * 12;
        unsigned long long bits = 0ULL;
        #pragma unroll
        for (int k = 0; k < 12; k++) {
            int w = w0 + k;
            unsigned long long isc =
                (unsigned long long)(lab[h * 48 + w] == (unsigned char)cgrp);
            bits |= isc << w;
        }
        if (bits) { atomicOr(&lmask[cgrp][h], bits); anyf[cgrp] = 1; }
    }
    __syncthreads();
    if (t == 0 && anyf[cgrp]) atomicOr(&g_flags[b * 4 + cgrp], 1);

    // Block 0 builds the sqrt LUT.
    if (bd == 0) {
        for (int i = tid; i < LUTN; i += 768) g_lut[i] = sqrtf((float)i);
    }

    // Exact W distances via clz/ffs (u16).
    #pragma unroll
    for (int k = 0; k < 12; k++) {
        int i = t + k * 192;
        int hh = i / 48;
        int ww = i - hh * 48;
        unsigned long long mm = lmask[cgrp][hh];
        unsigned long long lowm = mm << (63 - ww);
        unsigned long long him  = mm >> ww;
        int dl = lowm ? __clzll(lowm) : 99;
        int dr = him ? (__ffsll(him) - 1) : 99;
        int dd = min(dl, dr);
        us[cgrp][hh][ww] = (dd <= 47) ? (unsigned short)(dd * dd)
                                      : (unsigned short)U16INF;
    }
    __syncthreads();

    // H min-plus via DPX: grp owns x in [grp*12, grp*12+12) as 6 u16x2 accs;
    // lane = w.
    const int grp = t & 3;
    const int lane = t >> 2;
    unsigned int acc[6];
    #pragma unroll
    for (int k = 0; k < 6; k++) acc[k] = 0xFFFFFFFFu;

    #pragma unroll
    for (int j = 0; j < 48; j++) {
        unsigned int fj = us[cgrp][j][lane];
        unsigned int fj2 = fj * 0x00010001u;
        const unsigned int* qb = &psq[(j * 4 + grp) * 8];
        uint4 q4 = *(const uint4*)qb;
        uint2 q2 = *(const uint2*)(qb + 4);
        acc[0] = __viaddmin_u16x2(fj2, q4.x, acc[0]);
        acc[1] = __viaddmin_u16x2(fj2, q4.y, acc[1]);
        acc[2] = __viaddmin_u16x2(fj2, q4.z, acc[2]);
        acc[3] = __viaddmin_u16x2(fj2, q4.w, acc[3]);
        acc[4] = __viaddmin_u16x2(fj2, q2.x, acc[4]);
        acc[5] = __viaddmin_u16x2(fj2, q2.y, acc[5]);
    }

    const int base = (b * 4 + cgrp) * VOL + d * PLANE;
    #pragma unroll
    for (int kk = 0; kk < 6; kk++) {
        int x0 = grp * 12 + 2 * kk;
        g_bufS1[base + x0 * 48 + lane]       = (unsigned short)(acc[kk] & 0xFFFFu);
        g_bufS1[base + (x0 + 1) * 48 + lane] = (unsigned short)(acc[kk] >> 16);
    }
}

// ---------------------------------------------------------------------------
// Kernel B: exact D min-plus via DPX. One block per (m, h) plane (d, w),
// 192 threads. u16 in -> u16 out.
// ---------------------------------------------------------------------------
__global__ void __launch_bounds__(192) kB() {
    __shared__ unsigned short us[48][50];
    __shared__ unsigned int psq[48 * 4 * 8];

    const int tid = threadIdx.x;
    const int m = blockIdx.x / 48;
    const int h = blockIdx.x - m * 48;
    const int base = m * VOL + h * 48;

    fill_psq(psq, tid, 192);

    // Copy plane rows (u32 pairs: 1152 words).
    {
        const unsigned int* src = (const unsigned int*)(g_bufS1 + base);
        #pragma unroll
        for (int k = 0; k < 6; k++) {
            int p = tid + k * 192;          // pair index 0..1151
            int dd = p / 24;
            int wp = p - dd * 24;
            *(unsigned int*)&us[dd][wp * 2] = src[dd * (PLANE / 2) + wp];
        }
    }
    __syncthreads();

    const int grp = tid & 3;
    const int lane = tid >> 2;
    unsigned int acc[6];
    #pragma unroll
    for (int k = 0; k < 6; k++) acc[k] = 0xFFFFFFFFu;

    #pragma unroll
    for (int j = 0; j < 48; j++) {
        unsigned int fj = us[j][lane];
        unsigned int fj2 = fj * 0x00010001u;
        const unsigned int* qb = &psq[(j * 4 + grp) * 8];
        uint4 q4 = *(const uint4*)qb;
        uint2 q2 = *(const uint2*)(qb + 4);
        acc[0] = __viaddmin_u16x2(fj2, q4.x, acc[0]);
        acc[1] = __viaddmin_u16x2(fj2, q4.y, acc[1]);
        acc[2] = __viaddmin_u16x2(fj2, q4.z, acc[2]);
        acc[3] = __viaddmin_u16x2(fj2, q4.w, acc[3]);
        acc[4] = __viaddmin_u16x2(fj2, q2.x, acc[4]);
        acc[5] = __viaddmin_u16x2(fj2, q2.y, acc[5]);
    }

    #pragma unroll
    for (int kk = 0; kk < 6; kk++) {
        int x0 = grp * 12 + 2 * kk;
        g_bufS2[base + x0 * PLANE + lane]       = (unsigned short)(acc[kk] & 0xFFFFu);
        g_bufS2[base + (x0 + 1) * PLANE + lane] = (unsigned short)(acc[kk] >> 16);
    }
}

// ---------------------------------------------------------------------------
// Loss: 2 voxels/thread (float2 pred, ushort2 dist, front-batched MLP=8).
// q_c = LUT[pos2_c]; |sdf_c| = q_c + min_{c'!=c} q_{c'}. Branch-free flag
// multipliers. Deterministic double reduction; last block finishes + resets.
// ---------------------------------------------------------------------------
__global__ void __launch_bounds__(256) k_loss(const float* __restrict__ pred,
                                              float* __restrict__ out) {
    const int t = blockIdx.x * 256 + threadIdx.x;   // 0..110591
    const int b = t / HV;
    const int r = t - b * HV;
    const int base2 = b * 4 * HV + r;

    const float2*  p2 = (const float2*)pred;
    const ushort2* q2 = (const ushort2*)g_bufS2;

    float2  P[4];
    ushort2 Dv[4];
    #pragma unroll
    for (int c = 0; c < 4; c++) P[c] = __ldg(&p2[base2 + c * HV]);
    #pragma unroll
    for (int c = 0; c < 4; c++) Dv[c] = __ldg(&q2[base2 + c * HV]);

    float fl[4];
    #pragma unroll
    for (int c = 0; c < 4; c++) fl[c] = g_flags[b * 4 + c] ? 1.0f : 0.0f;

    double sum = 0.0;
    #pragma unroll
    for (int v = 0; v < 2; v++) {
        float p0 = v ? P[0].y : P[0].x;
        float p1 = v ? P[1].y : P[1].x;
        float p2v = v ? P[2].y : P[2].x;
        float p3 = v ? P[3].y : P[3].x;
        int i0 = v ? Dv[0].y : Dv[0].x;
        int i1 = v ? Dv[1].y : Dv[1].x;
        int i2 = v ? Dv[2].y : Dv[2].x;
        int i3 = v ? Dv[3].y : Dv[3].x;

        float q0 = (i0 < LUTN) ? __ldg(&g_lut[i0]) : sqrtf((float)i0);
        float q1 = (i1 < LUTN) ? __ldg(&g_lut[i1]) : sqrtf((float)i1);
        float q2c = (i2 < LUTN) ? __ldg(&g_lut[i2]) : sqrtf((float)i2);
        float q3 = (i3 < LUTN) ? __ldg(&g_lut[i3]) : sqrtf((float)i3);

        float mx = fmaxf(fmaxf(p0, p1), fmaxf(p2v, p3));
        float e0 = __expf(p0 - mx);
        float e1 = __expf(p1 - mx);
        float e2 = __expf(p2v - mx);
        float e3 = __expf(p3 - mx);
        float inv = __fdividef(1.0f, e0 + e1 + e2 + e3);

        float m01 = fminf(q0, q1), m23 = fminf(q2c, q3);
        float s0 = q0 + fminf(q1, m23);
        float s1 = q1 + fminf(q0, m23);
        float s2 = q2c + fminf(m01, q3);
        float s3 = q3 + fminf(m01, q2c);

        float local = fl[0] * e0 * s0 + fl[1] * e1 * s1
                    + fl[2] * e2 * s2 + fl[3] * e3 * s3;
        sum += (double)(local * inv);
    }

    __shared__ double sh[256];
    __shared__ int islast;
    sh[threadIdx.x] = sum;
    __syncthreads();
    #pragma unroll
    for (int st = 128; st > 0; st >>= 1) {
        if (threadIdx.x < st) sh[threadIdx.x] += sh[threadIdx.x + st];
        __syncthreads();
    }
    if (threadIdx.x == 0) {
        g_partials[blockIdx.x] = sh[0];
        __threadfence();
        int done = atomicAdd(&g_count, 1);
        islast = (done == gridDim.x - 1);
    }
    __syncthreads();

    if (islast) {
        int i2n = threadIdx.x + 256;
        double v = g_partials[threadIdx.x]
                 + ((i2n < LOSSBLKS) ? g_partials[i2n] : 0.0);
        sh[threadIdx.x] = v;
        __syncthreads();
        #pragma unroll
        for (int st = 128; st > 0; st >>= 1) {
            if (threadIdx.x < st) sh[threadIdx.x] += sh[threadIdx.x + st];
            __syncthreads();
        }
        if (threadIdx.x == 0) {
            out[0] = (float)(sh[0] / (double)TOTALE);
            g_count = 0;                    // reset for next graph replay
        }
        if (threadIdx.x < 8) g_flags[threadIdx.x] = 0;
    }
}

// ---------------------------------------------------------------------------
extern "C" void kernel_launch(void* const* d_in, const int* in_sizes, int n_in,
                              void* d_out, int out_size) {
    const float* pred   = (const float*)d_in[0];
    const void*  target = d_in[1];
    float* out = (float*)d_out;

    kA<<<96, 768>>>(target);            // labels -> W bit-scan + H DPX min-plus
    kB<<<8 * 48, 192>>>();              // D DPX min-plus
    k_loss<<<LOSSBLKS, 256>>>(pred, out);
}

// round 10
// speedup vs baseline: 1.3351x; 1.1506x over previous
#include <cuda_runtime.h>
#include <math.h>

#define VOL    110592   // 48*48*48
#define HV     55296    // VOL/2
#define PLANE  2304     // 48*48
#define NVOX   221184   // B * VOL
#define TOTALE 884736   // B*C*VOL
#define LUTN   6640
#define U16INF 50000    // 'infinity' in u16 domain; max transient 54418 < 65535
#define LOSSBLKS 432    // NVOX / 2 / 256

// Static scratch (no allocations allowed)
__device__ unsigned short g_bufS1[8 * VOL];  // pos^2 after W+H (u16)
__device__ unsigned short g_bufS2[8 * VOL];  // pos^2 after W+H+D (u16)
__device__ float  g_lut[LUTN];
__device__ int    g_flags[8];   // zero-init; reset by loss epilogue each replay
__device__ int    g_count;      // zero-init; reset by loss epilogue each replay
__device__ double g_partials[LOSSBLKS];

// psq table: entry ((j*8 + grp)*4 + kk), kk in [0,3) used (kk=3 pad=0):
//   x0 = grp*6 + 2*kk;  packed ( (x0-j)^2 , (x0+1-j)^2 )
// 48*8*4 words = 6 KB; 16B-aligned groups -> one LDS.128 per (j,grp).
__device__ __forceinline__ void fill_psq(unsigned int* psq, int tid, int nthr) {
    for (int i = tid; i < 48 * 8 * 4; i += nthr) {
        int j  = i >> 5;
        int g  = (i >> 2) & 7;
        int kk = i & 3;
        unsigned int val = 0;
        if (kk < 3) {
            int x0 = g * 6 + 2 * kk;
            int d0 = x0 - j;
            int d1 = d0 + 1;
            val = (unsigned int)(d0 * d0) | ((unsigned int)(d1 * d1) << 16);
        }
        psq[i] = val;
    }
}

// ---------------------------------------------------------------------------
// Kernel A: one block per (m=b*4+c, d) plane, 384 threads, 6 outputs/thread.
// dtype detect, labels (per-block re-read; DRAM is idle), class line masks,
// exact W-EDT via clz/ffs (u16), exact H min-plus via DPX u16x2.
// Block 0 also builds the sqrt LUT.
// ---------------------------------------------------------------------------
__global__ void __launch_bounds__(384) kA(const void* __restrict__ target) {
    __shared__ unsigned char lab[PLANE];
    __shared__ unsigned long long lmask[48];
    __shared__ unsigned short us[48][50];
    __shared__ unsigned int psq[48 * 8 * 4];
    __shared__ int sbad;
    __shared__ int anyflag;

    const int tid = threadIdx.x;
    const int m = blockIdx.x / 48;        // b*4 + c
    const int d = blockIdx.x - m * 48;
    const int b = m >> 2;
    const int c = m & 3;

    if (tid < 48) lmask[tid] = 0ULL;
    if (tid == 0) { sbad = 0; anyflag = 0; }
    __syncthreads();

    // dtype detection from the first 512 bytes (in-bounds for both dtypes).
    if (tid < 64) {
        long long v = ((const long long*)target)[tid];
        if (v < 0 || v > 3) atomicOr(&sbad, 1);
    }
    __syncthreads();
    const bool is64 = (sbad == 0);

    // Load this (b,d) plane's labels (6 iterations).
    const int vbase = b * VOL + d * PLANE;
    if (is64) {
        const long long* tp = (const long long*)target;
        #pragma unroll
        for (int k = 0; k < 6; k++) {
            int i = tid + k * 384;
            lab[i] = (unsigned char)tp[vbase + i];
        }
    } else {
        const int* tp = (const int*)target;
        #pragma unroll
        for (int k = 0; k < 6; k++) {
            int i = tid + k * 384;
            lab[i] = (unsigned char)tp[vbase + i];
        }
    }
    fill_psq(psq, tid, 384);
    __syncthreads();

    // Per-line seed bitmasks: thread owns 6 w of one line.
    {
        int h = tid >> 3;
        int w0 = (tid & 7) * 6;
        unsigned long long bits = 0ULL;
        #pragma unroll
        for (int k = 0; k < 6; k++) {
            int w = w0 + k;
            unsigned long long isc =
                (unsigned long long)(lab[h * 48 + w] == (unsigned char)c);
            bits |= isc << w;
        }
        if (bits) { atomicOr(&lmask[h], bits); anyflag = 1; }
    }
    __syncthreads();
    if (tid == 0 && anyflag) atomicOr(&g_flags[m], 1);

    // Block 0 builds the sqrt LUT.
    if (blockIdx.x == 0) {
        for (int i = tid; i < LUTN; i += 384) g_lut[i] = sqrtf((float)i);
    }

    // Exact W distances via clz/ffs (u16), 6 per thread.
    #pragma unroll
    for (int k = 0; k < 6; k++) {
        int i = tid + k * 384;
        int hh = i / 48;
        int ww = i - hh * 48;
        unsigned long long mm = lmask[hh];
        unsigned long long lowm = mm << (63 - ww);
        unsigned long long him  = mm >> ww;
        int dl = lowm ? __clzll(lowm) : 99;
        int dr = him ? (__ffsll(him) - 1) : 99;
        int dd = min(dl, dr);
        us[hh][ww] = (dd <= 47) ? (unsigned short)(dd * dd)
                                : (unsigned short)U16INF;
    }
    __syncthreads();

    // H min-plus via DPX: grp = tid/48 owns x in [grp*6, grp*6+6) as 3 accs;
    // lane = tid%48 = w. psq loads are warp-uniform -> smem broadcast.
    const int grp = tid / 48;
    const int lane = tid - grp * 48;
    unsigned int a0 = 0xFFFFFFFFu, a1 = 0xFFFFFFFFu, a2 = 0xFFFFFFFFu;

    #pragma unroll
    for (int j = 0; j < 48; j++) {
        unsigned int fj2 = (unsigned int)us[j][lane] * 0x00010001u;
        uint4 q = *(const uint4*)&psq[(j * 8 + grp) * 4];
        a0 = __viaddmin_u16x2(fj2, q.x, a0);
        a1 = __viaddmin_u16x2(fj2, q.y, a1);
        a2 = __viaddmin_u16x2(fj2, q.z, a2);
    }

    const int base = m * VOL + d * PLANE;
    const int x0 = grp * 6;
    g_bufS1[base + x0 * 48 + lane]       = (unsigned short)(a0 & 0xFFFFu);
    g_bufS1[base + (x0 + 1) * 48 + lane] = (unsigned short)(a0 >> 16);
    g_bufS1[base + (x0 + 2) * 48 + lane] = (unsigned short)(a1 & 0xFFFFu);
    g_bufS1[base + (x0 + 3) * 48 + lane] = (unsigned short)(a1 >> 16);
    g_bufS1[base + (x0 + 4) * 48 + lane] = (unsigned short)(a2 & 0xFFFFu);
    g_bufS1[base + (x0 + 5) * 48 + lane] = (unsigned short)(a2 >> 16);
}

// ---------------------------------------------------------------------------
// Kernel B: exact D min-plus via DPX. One block per (m, h) plane (d, w),
// 384 threads, 6 outputs/thread. u16 in -> u16 out.
// ---------------------------------------------------------------------------
__global__ void __launch_bounds__(384) kB() {
    __shared__ unsigned short us[48][50];
    __shared__ unsigned int psq[48 * 8 * 4];

    const int tid = threadIdx.x;
    const int m = blockIdx.x / 48;
    const int h = blockIdx.x - m * 48;
    const int base = m * VOL + h * 48;

    fill_psq(psq, tid, 384);

    // Load plane rows as u32 pairs (1152 words, 3 iterations).
    {
        const unsigned int* src = (const unsigned int*)(g_bufS1 + base);
        #pragma unroll
        for (int k = 0; k < 3; k++) {
            int p = tid + k * 384;          // pair index 0..1151
            int dd = p / 24;
            int wp = p - dd * 24;
            *(unsigned int*)&us[dd][wp * 2] = src[dd * (PLANE / 2) + wp];
        }
    }
    __syncthreads();

    const int grp = tid / 48;
    const int lane = tid - grp * 48;
    unsigned int a0 = 0xFFFFFFFFu, a1 = 0xFFFFFFFFu, a2 = 0xFFFFFFFFu;

    #pragma unroll
    for (int j = 0; j < 48; j++) {
        unsigned int fj2 = (unsigned int)us[j][lane] * 0x00010001u;
        uint4 q = *(const uint4*)&psq[(j * 8 + grp) * 4];
        a0 = __viaddmin_u16x2(fj2, q.x, a0);
        a1 = __viaddmin_u16x2(fj2, q.y, a1);
        a2 = __viaddmin_u16x2(fj2, q.z, a2);
    }

    const int x0 = grp * 6;
    g_bufS2[base + x0 * PLANE + lane]       = (unsigned short)(a0 & 0xFFFFu);
    g_bufS2[base + (x0 + 1) * PLANE + lane] = (unsigned short)(a0 >> 16);
    g_bufS2[base + (x0 + 2) * PLANE + lane] = (unsigned short)(a1 & 0xFFFFu);
    g_bufS2[base + (x0 + 3) * PLANE + lane] = (unsigned short)(a1 >> 16);
    g_bufS2[base + (x0 + 4) * PLANE + lane] = (unsigned short)(a2 & 0xFFFFu);
    g_bufS2[base + (x0 + 5) * PLANE + lane] = (unsigned short)(a2 >> 16);
}

// ---------------------------------------------------------------------------
// Loss: 2 voxels/thread (float2 pred, ushort2 dist, front-batched MLP=8).
// q_c = LUT[pos2_c]; |sdf_c| = q_c + min_{c'!=c} q_{c'}. Branch-free flag
// multipliers. Deterministic double reduction; last block finishes + resets.
// ---------------------------------------------------------------------------
__global__ void __launch_bounds__(256) k_loss(const float* __restrict__ pred,
                                              float* __restrict__ out) {
    const int t = blockIdx.x * 256 + threadIdx.x;   // 0..110591
    const int b = t / HV;
    const int r = t - b * HV;
    const int base2 = b * 4 * HV + r;

    const float2*  p2 = (const float2*)pred;
    const ushort2* q2 = (const ushort2*)g_bufS2;

    float2  P[4];
    ushort2 Dv[4];
    #pragma unroll
    for (int c = 0; c < 4; c++) P[c] = __ldg(&p2[base2 + c * HV]);
    #pragma unroll
    for (int c = 0; c < 4; c++) Dv[c] = __ldg(&q2[base2 + c * HV]);

    float fl[4];
    #pragma unroll
    for (int c = 0; c < 4; c++) fl[c] = g_flags[b * 4 + c] ? 1.0f : 0.0f;

    double sum = 0.0;
    #pragma unroll
    for (int v = 0; v < 2; v++) {
        float p0 = v ? P[0].y : P[0].x;
        float p1 = v ? P[1].y : P[1].x;
        float p2v = v ? P[2].y : P[2].x;
        float p3 = v ? P[3].y : P[3].x;
        int i0 = v ? Dv[0].y : Dv[0].x;
        int i1 = v ? Dv[1].y : Dv[1].x;
        int i2 = v ? Dv[2].y : Dv[2].x;
        int i3 = v ? Dv[3].y : Dv[3].x;

        float q0 = (i0 < LUTN) ? __ldg(&g_lut[i0]) : sqrtf((float)i0);
        float q1 = (i1 < LUTN) ? __ldg(&g_lut[i1]) : sqrtf((float)i1);
        float q2c = (i2 < LUTN) ? __ldg(&g_lut[i2]) : sqrtf((float)i2);
        float q3 = (i3 < LUTN) ? __ldg(&g_lut[i3]) : sqrtf((float)i3);

        float mx = fmaxf(fmaxf(p0, p1), fmaxf(p2v, p3));
        float e0 = __expf(p0 - mx);
        float e1 = __expf(p1 - mx);
        float e2 = __expf(p2v - mx);
        float e3 = __expf(p3 - mx);
        float inv = __fdividef(1.0f, e0 + e1 + e2 + e3);

        float m01 = fminf(q0, q1), m23 = fminf(q2c, q3);
        float s0 = q0 + fminf(q1, m23);
        float s1 = q1 + fminf(q0, m23);
        float s2 = q2c + fminf(m01, q3);
        float s3 = q3 + fminf(m01, q2c);

        float local = fl[0] * e0 * s0 + fl[1] * e1 * s1
                    + fl[2] * e2 * s2 + fl[3] * e3 * s3;
        sum += (double)(local * inv);
    }

    __shared__ double sh[256];
    __shared__ int islast;
    sh[threadIdx.x] = sum;
    __syncthreads();
    #pragma unroll
    for (int st = 128; st > 0; st >>= 1) {
        if (threadIdx.x < st) sh[threadIdx.x] += sh[threadIdx.x + st];
        __syncthreads();
    }
    if (threadIdx.x == 0) {
        g_partials[blockIdx.x] = sh[0];
        __threadfence();
        int done = atomicAdd(&g_count, 1);
        islast = (done == gridDim.x - 1);
    }
    __syncthreads();

    if (islast) {
        int i2n = threadIdx.x + 256;
        double v = g_partials[threadIdx.x]
                 + ((i2n < LOSSBLKS) ? g_partials[i2n] : 0.0);
        sh[threadIdx.x] = v;
        __syncthreads();
        #pragma unroll
        for (int st = 128; st > 0; st >>= 1) {
            if (threadIdx.x < st) sh[threadIdx.x] += sh[threadIdx.x + st];
            __syncthreads();
        }
        if (threadIdx.x == 0) {
            out[0] = (float)(sh[0] / (double)TOTALE);
            g_count = 0;                    // reset for next graph replay
        }
        if (threadIdx.x < 8) g_flags[threadIdx.x] = 0;
    }
}

// ---------------------------------------------------------------------------
extern "C" void kernel_launch(void* const* d_in, const int* in_sizes, int n_in,
                              void* d_out, int out_size) {
    const float* pred   = (const float*)d_in[0];
    const void*  target = d_in[1];
    float* out = (float*)d_out;

    kA<<<8 * 48, 384>>>(target);        // W bit-scan + H DPX min-plus
    kB<<<8 * 48, 384>>>();              // D DPX min-plus
    k_loss<<<LOSSBLKS, 256>>>(pred, out);
}

// round 11
// speedup vs baseline: 1.3535x; 1.0138x over previous
#include <cuda_runtime.h>
#include <math.h>

#define VOL    110592   // 48*48*48
#define HV     55296    // VOL/2
#define PLANE  2304     // 48*48
#define NVOX   221184   // B * VOL
#define TOTALE 884736   // B*C*VOL
#define U16INF 50000    // 'infinity' in u16 domain; max transient 54418 < 65535
#define LOSSBLKS 432    // NVOX / 2 / 256

// Static scratch (no allocations allowed)
__device__ unsigned short g_bufS1[8 * VOL];  // pos^2 after W+H (u16)
__device__ unsigned short g_bufS2[8 * VOL];  // pos^2 after W+H+D (u16)
__device__ float  g_lut[65536];              // sqrt LUT, full u16 range
__device__ int    g_flags[8];   // zero-init; reset by loss epilogue each replay
__device__ int    g_count;      // zero-init; reset by loss epilogue each replay
__device__ double g_partials[LOSSBLKS];

// psq table: entry ((j*8 + grp)*4 + kk), kk in [0,3) used (kk=3 pad=0):
//   x0 = grp*6 + 2*kk;  packed ( (x0-j)^2 , (x0+1-j)^2 )
__device__ __forceinline__ void fill_psq(unsigned int* psq, int tid, int nthr) {
    for (int i = tid; i < 48 * 8 * 4; i += nthr) {
        int j  = i >> 5;
        int g  = (i >> 2) & 7;
        int kk = i & 3;
        unsigned int val = 0;
        if (kk < 3) {
            int x0 = g * 6 + 2 * kk;
            int d0 = x0 - j;
            int d1 = d0 + 1;
            val = (unsigned int)(d0 * d0) | ((unsigned int)(d1 * d1) << 16);
        }
        psq[i] = val;
    }
}

// ---------------------------------------------------------------------------
// Kernel A: one block per (m=b*4+c, d) plane, 384 threads.
// Labels loaded straight into registers (thread owns its contiguous 6-label
// mask chunk), per-class line masks, exact W-EDT via clz/ffs (u16),
// exact H min-plus via DPX u16x2. Blocks 0..15 fill the sqrt LUT.
// ---------------------------------------------------------------------------
__global__ void __launch_bounds__(384) kA(const void* __restrict__ target) {
    __shared__ unsigned long long lmask[48];
    __shared__ unsigned short us[48][50];
    __shared__ unsigned int psq[48 * 8 * 4];
    __shared__ int sbad;
    __shared__ int anyflag;

    const int tid = threadIdx.x;
    const int m = blockIdx.x / 48;        // b*4 + c
    const int d = blockIdx.x - m * 48;
    const int b = m >> 2;
    const int c = m & 3;

    if (tid < 48) lmask[tid] = 0ULL;
    if (tid == 0) { sbad = 0; anyflag = 0; }
    fill_psq(psq, tid, 384);
    __syncthreads();

    // dtype detection from the first 512 bytes (in-bounds for both dtypes).
    if (tid < 64) {
        long long v = ((const long long*)target)[tid];
        if (v < 0 || v > 3) atomicOr(&sbad, 1);
    }
    __syncthreads();
    const bool is64 = (sbad == 0);

    // Load this thread's 6 contiguous labels into registers.
    // element index = b*VOL + d*PLANE + tid*6 + {0..5}
    const int ebase = b * VOL + d * PLANE + tid * 6;
    unsigned char lb[6];
    if (is64) {
        const longlong2* tp = (const longlong2*)((const long long*)target + ebase);
        longlong2 v0 = __ldg(&tp[0]);
        longlong2 v1 = __ldg(&tp[1]);
        longlong2 v2 = __ldg(&tp[2]);
        lb[0] = (unsigned char)v0.x; lb[1] = (unsigned char)v0.y;
        lb[2] = (unsigned char)v1.x; lb[3] = (unsigned char)v1.y;
        lb[4] = (unsigned char)v2.x; lb[5] = (unsigned char)v2.y;
    } else {
        const int2* tp = (const int2*)((const int*)target + ebase);
        int2 v0 = __ldg(&tp[0]);
        int2 v1 = __ldg(&tp[1]);
        int2 v2 = __ldg(&tp[2]);
        lb[0] = (unsigned char)v0.x; lb[1] = (unsigned char)v0.y;
        lb[2] = (unsigned char)v1.x; lb[3] = (unsigned char)v1.y;
        lb[4] = (unsigned char)v2.x; lb[5] = (unsigned char)v2.y;
    }

    // Build this thread's 6-bit mask chunk: h = tid/8, w0 = (tid%8)*6.
    {
        const int w0 = (tid & 7) * 6;
        unsigned long long bits = 0ULL;
        #pragma unroll
        for (int k = 0; k < 6; k++) {
            unsigned long long isc = (unsigned long long)(lb[k] == (unsigned char)c);
            bits |= isc << (w0 + k);
        }
        if (bits) { atomicOr(&lmask[tid >> 3], bits); anyflag = 1; }
    }

    // Blocks 0..15 fill the full-range sqrt LUT (4096 entries each).
    if (blockIdx.x < 16) {
        const int lbase = blockIdx.x * 4096;
        #pragma unroll
        for (int k = 0; k < 11; k++) {
            int i = tid + k * 384;
            if (i < 4096) g_lut[lbase + i] = sqrtf((float)(lbase + i));
        }
    }
    __syncthreads();
    if (tid == 0 && anyflag) atomicOr(&g_flags[m], 1);

    // Exact W distances via clz/ffs (u16), 6 per thread.
    #pragma unroll
    for (int k = 0; k < 6; k++) {
        int i = tid + k * 384;
        int hh = i / 48;
        int ww = i - hh * 48;
        unsigned long long mm = lmask[hh];
        unsigned long long lowm = mm << (63 - ww);
        unsigned long long him  = mm >> ww;
        int dl = lowm ? __clzll(lowm) : 99;
        int dr = him ? (__ffsll(him) - 1) : 99;
        int dd = min(dl, dr);
        us[hh][ww] = (dd <= 47) ? (unsigned short)(dd * dd)
                                : (unsigned short)U16INF;
    }
    __syncthreads();

    // H min-plus via DPX: grp = tid/48 owns x in [grp*6, grp*6+6); lane = w.
    const int grp = tid / 48;
    const int lane = tid - grp * 48;
    unsigned int a0 = 0xFFFFFFFFu, a1 = 0xFFFFFFFFu, a2 = 0xFFFFFFFFu;

    #pragma unroll
    for (int j = 0; j < 48; j++) {
        unsigned int fj2 = (unsigned int)us[j][lane] * 0x00010001u;
        uint4 q = *(const uint4*)&psq[(j * 8 + grp) * 4];
        a0 = __viaddmin_u16x2(fj2, q.x, a0);
        a1 = __viaddmin_u16x2(fj2, q.y, a1);
        a2 = __viaddmin_u16x2(fj2, q.z, a2);
    }

    const int base = m * VOL + d * PLANE;
    const int x0 = grp * 6;
    g_bufS1[base + x0 * 48 + lane]       = (unsigned short)(a0 & 0xFFFFu);
    g_bufS1[base + (x0 + 1) * 48 + lane] = (unsigned short)(a0 >> 16);
    g_bufS1[base + (x0 + 2) * 48 + lane] = (unsigned short)(a1 & 0xFFFFu);
    g_bufS1[base + (x0 + 3) * 48 + lane] = (unsigned short)(a1 >> 16);
    g_bufS1[base + (x0 + 4) * 48 + lane] = (unsigned short)(a2 & 0xFFFFu);
    g_bufS1[base + (x0 + 5) * 48 + lane] = (unsigned short)(a2 >> 16);
}

// ---------------------------------------------------------------------------
// Kernel B: exact D min-plus via DPX. One block per (m, h) plane (d, w),
// 384 threads, 6 outputs/thread. u16 in -> u16 out.
// ---------------------------------------------------------------------------
__global__ void __launch_bounds__(384) kB() {
    __shared__ unsigned short us[48][50];
    __shared__ unsigned int psq[48 * 8 * 4];

    const int tid = threadIdx.x;
    const int m = blockIdx.x / 48;
    const int h = blockIdx.x - m * 48;
    const int base = m * VOL + h * 48;

    fill_psq(psq, tid, 384);

    // Load plane rows as u32 pairs (1152 words, 3 iterations).
    {
        const unsigned int* src = (const unsigned int*)(g_bufS1 + base);
        #pragma unroll
        for (int k = 0; k < 3; k++) {
            int p = tid + k * 384;          // pair index 0..1151
            int dd = p / 24;
            int wp = p - dd * 24;
            *(unsigned int*)&us[dd][wp * 2] = src[dd * (PLANE / 2) + wp];
        }
    }
    __syncthreads();

    const int grp = tid / 48;
    const int lane = tid - grp * 48;
    unsigned int a0 = 0xFFFFFFFFu, a1 = 0xFFFFFFFFu, a2 = 0xFFFFFFFFu;

    #pragma unroll
    for (int j = 0; j < 48; j++) {
        unsigned int fj2 = (unsigned int)us[j][lane] * 0x00010001u;
        uint4 q = *(const uint4*)&psq[(j * 8 + grp) * 4];
        a0 = __viaddmin_u16x2(fj2, q.x, a0);
        a1 = __viaddmin_u16x2(fj2, q.y, a1);
        a2 = __viaddmin_u16x2(fj2, q.z, a2);
    }

    const int x0 = grp * 6;
    g_bufS2[base + x0 * PLANE + lane]       = (unsigned short)(a0 & 0xFFFFu);
    g_bufS2[base + (x0 + 1) * PLANE + lane] = (unsigned short)(a0 >> 16);
    g_bufS2[base + (x0 + 2) * PLANE + lane] = (unsigned short)(a1 & 0xFFFFu);
    g_bufS2[base + (x0 + 3) * PLANE + lane] = (unsigned short)(a1 >> 16);
    g_bufS2[base + (x0 + 4) * PLANE + lane] = (unsigned short)(a2 & 0xFFFFu);
    g_bufS2[base + (x0 + 5) * PLANE + lane] = (unsigned short)(a2 >> 16);
}

// ---------------------------------------------------------------------------
// Loss: 2 voxels/thread (float2 pred, ushort2 dist, front-batched MLP=8).
// q_c = LUT[pos2_c] (full-range LUT, no branches);
// |sdf_c| = q_c + min_{c'!=c} q_{c'}. Branch-free flag multipliers.
// Deterministic double reduction; last block finishes + resets globals.
// ---------------------------------------------------------------------------
__global__ void __launch_bounds__(256) k_loss(const float* __restrict__ pred,
                                              float* __restrict__ out) {
    const int t = blockIdx.x * 256 + threadIdx.x;   // 0..110591
    const int b = t / HV;
    const int r = t - b * HV;
    const int base2 = b * 4 * HV + r;

    const float2*  p2 = (const float2*)pred;
    const ushort2* q2 = (const ushort2*)g_bufS2;

    float2  P[4];
    ushort2 Dv[4];
    #pragma unroll
    for (int c = 0; c < 4; c++) P[c] = __ldg(&p2[base2 + c * HV]);
    #pragma unroll
    for (int c = 0; c < 4; c++) Dv[c] = __ldg(&q2[base2 + c * HV]);

    float fl[4];
    #pragma unroll
    for (int c = 0; c < 4; c++) fl[c] = g_flags[b * 4 + c] ? 1.0f : 0.0f;

    double sum = 0.0;
    #pragma unroll
    for (int v = 0; v < 2; v++) {
        float p0 = v ? P[0].y : P[0].x;
        float p1 = v ? P[1].y : P[1].x;
        float p2v = v ? P[2].y : P[2].x;
        float p3 = v ? P[3].y : P[3].x;
        int i0 = v ? Dv[0].y : Dv[0].x;
        int i1 = v ? Dv[1].y : Dv[1].x;
        int i2 = v ? Dv[2].y : Dv[2].x;
        int i3 = v ? Dv[3].y : Dv[3].x;

        float q0 = __ldg(&g_lut[i0]);
        float q1 = __ldg(&g_lut[i1]);
        float q2c = __ldg(&g_lut[i2]);
        float q3 = __ldg(&g_lut[i3]);

        float mx = fmaxf(fmaxf(p0, p1), fmaxf(p2v, p3));
        float e0 = __expf(p0 - mx);
        float e1 = __expf(p1 - mx);
        float e2 = __expf(p2v - mx);
        float e3 = __expf(p3 - mx);
        float inv = __fdividef(1.0f, e0 + e1 + e2 + e3);

        float m01 = fminf(q0, q1), m23 = fminf(q2c, q3);
        float s0 = q0 + fminf(q1, m23);
        float s1 = q1 + fminf(q0, m23);
        float s2 = q2c + fminf(m01, q3);
        float s3 = q3 + fminf(m01, q2c);

        float local = fl[0] * e0 * s0 + fl[1] * e1 * s1
                    + fl[2] * e2 * s2 + fl[3] * e3 * s3;
        sum += (double)(local * inv);
    }

    __shared__ double sh[256];
    __shared__ int islast;
    sh[threadIdx.x] = sum;
    __syncthreads();
    #pragma unroll
    for (int st = 128; st > 0; st >>= 1) {
        if (threadIdx.x < st) sh[threadIdx.x] += sh[threadIdx.x + st];
        __syncthreads();
    }
    if (threadIdx.x == 0) {
        g_partials[blockIdx.x] = sh[0];
        __threadfence();
        int done = atomicAdd(&g_count, 1);
        islast = (done == gridDim.x - 1);
    }
    __syncthreads();

    if (islast) {
        int i2n = threadIdx.x + 256;
        double v = g_partials[threadIdx.x]
                 + ((i2n < LOSSBLKS) ? g_partials[i2n] : 0.0);
        sh[threadIdx.x] = v;
        __syncthreads();
        #pragma unroll
        for (int st = 128; st > 0; st >>= 1) {
            if (threadIdx.x < st) sh[threadIdx.x] += sh[threadIdx.x + st];
            __syncthreads();
        }
        if (threadIdx.x == 0) {
            out[0] = (float)(sh[0] / (double)TOTALE);
            g_count = 0;                    // reset for next graph replay
        }
        if (threadIdx.x < 8) g_flags[threadIdx.x] = 0;
    }
}

// ---------------------------------------------------------------------------
extern "C" void kernel_launch(void* const* d_in, const int* in_sizes, int n_in,
                              void* d_out, int out_size) {
    const float* pred   = (const float*)d_in[0];
    const void*  target = d_in[1];
    float* out = (float*)d_out;

    kA<<<8 * 48, 384>>>(target);        // W bit-scan + H DPX min-plus
    kB<<<8 * 48, 384>>>();              // D DPX min-plus
    k_loss<<<LOSSBLKS, 256>>>(pred, out);
}